// round 1
// baseline (speedup 1.0000x reference)
#include <cuda_runtime.h>
#include <cuda_bf16.h>
#include <math.h>

#define NN      8192
#define NFEAT   512
#define NHID    64
#define NHEADS  8
#define NCLASS  40
#define CHUNK   128
#define NCHUNKS (NN / CHUNK)   // 64

// ----------------------------- scratch (static device globals) ---------------
__device__ float g_Bpack[NFEAT * NHEADS * NHID];          // 512x512 repacked W_heads
__device__ float g_Wh1[NN * NHEADS * NHID];               // layer1 Wh (pre-attention)
__device__ float g_H[NN * NHEADS * NHID];                 // layer1 output / layer2 input
__device__ float g_Wh2[NN * NCLASS];                      // layer2 Wh
__device__ float g_O2[NN * NCLASS];                       // layer2 post-elu, pre-logsoftmax
__device__ float g_f1[NHEADS * NN];
__device__ float g_f2[NHEADS * NN];
__device__ float g_key[NHEADS * NN];                      // sorted f2 (desc)
__device__ int   g_perm[NHEADS * NN];
__device__ float g_w[NHEADS * NN];                        // exp(key - keymax)
__device__ float g_mean[NHEADS * 64];
__device__ float g_P[NHEADS * (NN + 1) * NHID];           // weighted prefix sums
__device__ float g_S[NHEADS * (NN + 1)];
__device__ float g_P2[(NN + 1) * NCLASS];
__device__ float g_S2[(NN + 1)];
__device__ float g_chunkP[NHEADS * NCHUNKS * 64];
__device__ float g_chunkS[NHEADS * NCHUNKS];

// ----------------------------- kernels --------------------------------------

// Repack W_heads[h, k, d] -> B[k, h*64+d]  (so layer1 is one plain GEMM)
__global__ void repack_W_kernel(const float* __restrict__ Wh, float* __restrict__ Bp) {
    int idx = blockIdx.x * blockDim.x + threadIdx.x;
    if (idx < NFEAT * NHEADS * NHID) {
        int n = idx % (NHEADS * NHID);
        int k = idx / (NHEADS * NHID);
        int h = n / NHID, d = n % NHID;
        Bp[idx] = Wh[(h * NFEAT + k) * NHID + d];
    }
}

// Row-major SGEMM: C[M,Ncols] = A[M,K] @ B[K,Ncols]. 128x128x8 tiles, 8x8 micro.
#define BM 128
#define BN 128
#define BKK 8
#define TM 8
#define TN 8
__global__ __launch_bounds__(256) void sgemm_kernel(
    int M, int Ncols, int K,
    const float* __restrict__ A, const float* __restrict__ B, float* __restrict__ C)
{
    __shared__ float As[BKK][BM];
    __shared__ float Bs[BKK][BN];
    int tid = threadIdx.x;
    int tx = tid % (BN / TN);   // 0..15
    int ty = tid / (BN / TN);   // 0..15
    int bm = blockIdx.y * BM, bn = blockIdx.x * BN;
    float acc[TM][TN];
#pragma unroll
    for (int i = 0; i < TM; i++)
#pragma unroll
        for (int j = 0; j < TN; j++) acc[i][j] = 0.f;

    for (int k0 = 0; k0 < K; k0 += BKK) {
        {
            int aRow = tid >> 1, aCol = (tid & 1) * 4;
#pragma unroll
            for (int i = 0; i < 4; i++) {
                float v = 0.f;
                int gr = bm + aRow, gc = k0 + aCol + i;
                if (gr < M) v = A[(size_t)gr * K + gc];
                As[aCol + i][aRow] = v;
            }
            int bRow = tid >> 5, bCol = (tid & 31) * 4;
#pragma unroll
            for (int i = 0; i < 4; i++) {
                float v = 0.f;
                int gc = bn + bCol + i;
                if (gc < Ncols) v = B[(size_t)(k0 + bRow) * Ncols + gc];
                Bs[bRow][bCol + i] = v;
            }
        }
        __syncthreads();
#pragma unroll
        for (int kk = 0; kk < BKK; kk++) {
            float ar[TM], br[TN];
#pragma unroll
            for (int i = 0; i < TM; i++) ar[i] = As[kk][ty * TM + i];
#pragma unroll
            for (int j = 0; j < TN; j++) br[j] = Bs[kk][tx * TN + j];
#pragma unroll
            for (int i = 0; i < TM; i++)
#pragma unroll
                for (int j = 0; j < TN; j++) acc[i][j] += ar[i] * br[j];
        }
        __syncthreads();
    }
#pragma unroll
    for (int i = 0; i < TM; i++) {
        int gr = bm + ty * TM + i;
        if (gr >= M) continue;
#pragma unroll
        for (int j = 0; j < TN; j++) {
            int gc = bn + tx * TN + j;
            if (gc < Ncols) C[(size_t)gr * Ncols + gc] = acc[i][j];
        }
    }
}

// f1[i] = Wh_row . a[0:F], f2[i] = Wh_row . a[F:2F]; one warp per (row, head)
__global__ void compute_f_kernel(
    const float* __restrict__ Wh, int ld, int F,
    const float* __restrict__ a, int aStride, int nHeads,
    float* __restrict__ f1, float* __restrict__ f2)
{
    int warpId = (blockIdx.x * blockDim.x + threadIdx.x) >> 5;
    int lane = threadIdx.x & 31;
    int total = NN * nHeads;
    if (warpId >= total) return;
    int h = warpId % nHeads;
    int i = warpId / nHeads;
    const float* av = a + h * aStride;
    const float* row = Wh + (size_t)i * ld + h * F;
    float s1 = 0.f, s2 = 0.f;
    for (int d = lane; d < F; d += 32) {
        float v = row[d];
        s1 += v * av[d];
        s2 += v * av[F + d];
    }
#pragma unroll
    for (int o = 16; o; o >>= 1) {
        s1 += __shfl_down_sync(0xFFFFFFFFu, s1, o);
        s2 += __shfl_down_sync(0xFFFFFFFFu, s2, o);
    }
    if (lane == 0) { f1[h * NN + i] = s1; f2[h * NN + i] = s2; }
}

// Bitonic sort 8192 keys (descending) with index payload, one block per head.
__global__ __launch_bounds__(1024) void sort_desc_kernel(
    const float* __restrict__ f2, float* __restrict__ keyOut, int* __restrict__ permOut)
{
    __shared__ float skey[NN];
    __shared__ unsigned short sidx[NN];
    int h = blockIdx.x;
    const float* src = f2 + h * NN;
    for (int t = threadIdx.x; t < NN; t += blockDim.x) { skey[t] = src[t]; sidx[t] = (unsigned short)t; }
    __syncthreads();
    for (int k = 2; k <= NN; k <<= 1) {
        for (int j = k >> 1; j > 0; j >>= 1) {
            for (int t = threadIdx.x; t < NN; t += blockDim.x) {
                int ixj = t ^ j;
                if (ixj > t) {
                    float a = skey[t], b = skey[ixj];
                    bool sw = ((t & k) == 0) ? (a < b) : (a > b);
                    if (sw) {
                        skey[t] = b; skey[ixj] = a;
                        unsigned short ti = sidx[t]; sidx[t] = sidx[ixj]; sidx[ixj] = ti;
                    }
                }
            }
            __syncthreads();
        }
    }
    for (int t = threadIdx.x; t < NN; t += blockDim.x) {
        keyOut[h * NN + t] = skey[t];
        permOut[h * NN + t] = (int)sidx[t];
    }
}

// w[r] = exp(key[r] - key[0])   (key sorted descending => key[0] is max)
__global__ void compute_w_kernel(const float* __restrict__ key, float* __restrict__ w, int nHeads) {
    int idx = blockIdx.x * blockDim.x + threadIdx.x;
    if (idx < nHeads * NN) {
        int h = idx / NN;
        w[idx] = expf(key[idx] - key[h * NN]);
    }
}

// Unweighted column means of Wh (for the empty-mask uniform-softmax case)
__global__ void col_mean_kernel(const float* __restrict__ Wh, int ld, int F, float* __restrict__ mean) {
    int d = blockIdx.x, h = blockIdx.y;
    float s = 0.f;
    for (int i = threadIdx.x; i < NN; i += blockDim.x)
        s += Wh[(size_t)i * ld + h * F + d];
    __shared__ float red[256];
    red[threadIdx.x] = s;
    __syncthreads();
    for (int o = 128; o; o >>= 1) {
        if (threadIdx.x < o) red[threadIdx.x] += red[threadIdx.x + o];
        __syncthreads();
    }
    if (threadIdx.x == 0) mean[h * 64 + d] = red[0] / (float)NN;
}

// Pass A: per-chunk weighted sums
__global__ void chunk_sums_kernel(
    const float* __restrict__ Wh, int ld, int F,
    const int* __restrict__ perm, const float* __restrict__ w,
    float* __restrict__ chunkP, float* __restrict__ chunkS)
{
    int c = blockIdx.x, h = blockIdx.y, d = threadIdx.x;
    const int* pm = perm + h * NN + c * CHUNK;
    const float* ww = w + h * NN + c * CHUNK;
    float acc = 0.f, accS = 0.f;
    for (int r = 0; r < CHUNK; r++) {
        float wr = ww[r];
        if (d < F) acc += wr * Wh[(size_t)pm[r] * ld + h * F + d];
        if (d == 0) accS += wr;
    }
    if (d < F) chunkP[(h * NCHUNKS + c) * 64 + d] = acc;
    if (d == 0) chunkS[h * NCHUNKS + c] = accS;
}

// Pass B: exclusive scan of chunk sums (in place -> chunk offsets)
__global__ void scan_chunks_kernel(float* __restrict__ chunkP, float* __restrict__ chunkS, int F) {
    int h = blockIdx.x, d = threadIdx.x;
    if (d < F) {
        float acc = 0.f;
        for (int c = 0; c < NCHUNKS; c++) {
            int idx = (h * NCHUNKS + c) * 64 + d;
            float t = chunkP[idx]; chunkP[idx] = acc; acc += t;
        }
    }
    if (d == 0) {
        float acc = 0.f;
        for (int c = 0; c < NCHUNKS; c++) {
            int idx = h * NCHUNKS + c;
            float t = chunkS[idx]; chunkS[idx] = acc; acc += t;
        }
    }
}

// Pass C: write full inclusive prefix arrays P[1..N], S[1..N]
__global__ void write_prefix_kernel(
    const float* __restrict__ Wh, int ld, int F,
    const int* __restrict__ perm, const float* __restrict__ w,
    const float* __restrict__ chunkP, const float* __restrict__ chunkS,
    float* __restrict__ P, float* __restrict__ S)
{
    int c = blockIdx.x, h = blockIdx.y, d = threadIdx.x;
    const int* pm = perm + h * NN + c * CHUNK;
    const float* ww = w + h * NN + c * CHUNK;
    float acc = (d < F) ? chunkP[(h * NCHUNKS + c) * 64 + d] : 0.f;
    float accS = chunkS[h * NCHUNKS + c];
    float* Ph = P + (size_t)h * (NN + 1) * F;
    float* Sh = S + (size_t)h * (NN + 1);
    for (int r = 0; r < CHUNK; r++) {
        float wr = ww[r];
        if (d < F) {
            acc += wr * Wh[(size_t)pm[r] * ld + h * F + d];
            Ph[(size_t)(c * CHUNK + r + 1) * F + d] = acc;
        }
        if (d == 0) { accS += wr; Sh[c * CHUNK + r + 1] = accS; }
    }
}

// Apply attention: binary search threshold, divide prefix, elu, scatter.
__global__ void apply_attn_kernel(
    const float* __restrict__ key, const float* __restrict__ f1,
    const float* __restrict__ P, const float* __restrict__ S,
    const float* __restrict__ mean, int F, int nHeads,
    float* __restrict__ out, int ldOut)
{
    int g = (blockIdx.x * blockDim.x + threadIdx.x) >> 6;
    int d = threadIdx.x & 63;
    int total = NN * nHeads;
    if (g >= total) return;
    int h = g % nHeads;
    int i = g / nHeads;
    const float* kh = key + h * NN;
    float t = f1[h * NN + i];
    // count of j with t + key[j] > 0 on descending keys
    int lo = 0, hi = NN;
    while (lo < hi) {
        int mid = (lo + hi) >> 1;
        if (t + kh[mid] > 0.f) lo = mid + 1; else hi = mid;
    }
    int c = lo;
    if (d < F) {
        float v;
        if (c > 0) {
            v = P[((size_t)h * (NN + 1) + c) * F + d] / S[(size_t)h * (NN + 1) + c];
        } else {
            v = mean[h * 64 + d];
        }
        v = (v > 0.f) ? v : (expf(v) - 1.f);   // ELU (alpha=1)
        out[(size_t)i * ldOut + h * F + d] = v;
    }
}

// Row log_softmax over NCLASS=40, one warp per row (two values per lane)
__global__ void log_softmax_kernel(const float* __restrict__ X, float* __restrict__ out) {
    int i = blockIdx.x * (blockDim.x >> 5) + (threadIdx.x >> 5);
    int lane = threadIdx.x & 31;
    if (i >= NN) return;
    const float* row = X + (size_t)i * NCLASS;
    float v0 = (lane < NCLASS) ? row[lane] : -INFINITY;
    float v1 = (lane + 32 < NCLASS) ? row[lane + 32] : -INFINITY;
    float mx = fmaxf(v0, v1);
#pragma unroll
    for (int o = 16; o; o >>= 1) mx = fmaxf(mx, __shfl_xor_sync(0xFFFFFFFFu, mx, o));
    float se = 0.f;
    if (lane < NCLASS) se += expf(v0 - mx);
    if (lane + 32 < NCLASS) se += expf(v1 - mx);
#pragma unroll
    for (int o = 16; o; o >>= 1) se += __shfl_xor_sync(0xFFFFFFFFu, se, o);
    float lse = mx + logf(se);
    if (lane < NCLASS) out[(size_t)i * NCLASS + lane] = v0 - lse;
    if (lane + 32 < NCLASS) out[(size_t)i * NCLASS + lane + 32] = v1 - lse;
}

// ----------------------------- host launcher --------------------------------
extern "C" void kernel_launch(void* const* d_in, const int* in_sizes, int n_in,
                              void* d_out, int out_size)
{
    const float* x       = (const float*)d_in[0];
    // d_in[1] = adj (unused by the math, replicating the reference)
    const float* W_heads = (const float*)d_in[2];
    const float* a_heads = (const float*)d_in[3];
    const float* W_out   = (const float*)d_in[4];
    const float* a_out   = (const float*)d_in[5];
    float* out = (float*)d_out;

    float *Bp, *Wh1, *H, *Wh2, *O2, *f1, *f2, *key, *w, *meanb, *P, *S, *P2, *S2, *chunkP, *chunkS;
    int* perm;
    cudaGetSymbolAddress((void**)&Bp,    g_Bpack);
    cudaGetSymbolAddress((void**)&Wh1,   g_Wh1);
    cudaGetSymbolAddress((void**)&H,     g_H);
    cudaGetSymbolAddress((void**)&Wh2,   g_Wh2);
    cudaGetSymbolAddress((void**)&O2,    g_O2);
    cudaGetSymbolAddress((void**)&f1,    g_f1);
    cudaGetSymbolAddress((void**)&f2,    g_f2);
    cudaGetSymbolAddress((void**)&key,   g_key);
    cudaGetSymbolAddress((void**)&perm,  g_perm);
    cudaGetSymbolAddress((void**)&w,     g_w);
    cudaGetSymbolAddress((void**)&meanb, g_mean);
    cudaGetSymbolAddress((void**)&P,     g_P);
    cudaGetSymbolAddress((void**)&S,     g_S);
    cudaGetSymbolAddress((void**)&P2,    g_P2);
    cudaGetSymbolAddress((void**)&S2,    g_S2);
    cudaGetSymbolAddress((void**)&chunkP, g_chunkP);
    cudaGetSymbolAddress((void**)&chunkS, g_chunkS);

    // ---------------- layer 1 (8 heads, fused as one GEMM) ----------------
    repack_W_kernel<<<(NFEAT * NHEADS * NHID + 255) / 256, 256>>>(W_heads, Bp);
    {
        dim3 grid((NHEADS * NHID + BN - 1) / BN, (NN + BM - 1) / BM);
        sgemm_kernel<<<grid, 256>>>(NN, NHEADS * NHID, NFEAT, x, Bp, Wh1);
    }
    compute_f_kernel<<<(NN * NHEADS * 32) / 128, 128>>>(Wh1, NHEADS * NHID, NHID,
                                                        a_heads, 2 * NHID, NHEADS, f1, f2);
    sort_desc_kernel<<<NHEADS, 1024>>>(f2, key, perm);
    compute_w_kernel<<<(NHEADS * NN + 255) / 256, 256>>>(key, w, NHEADS);
    col_mean_kernel<<<dim3(NHID, NHEADS), 256>>>(Wh1, NHEADS * NHID, NHID, meanb);
    chunk_sums_kernel<<<dim3(NCHUNKS, NHEADS), 64>>>(Wh1, NHEADS * NHID, NHID, perm, w, chunkP, chunkS);
    scan_chunks_kernel<<<NHEADS, 64>>>(chunkP, chunkS, NHID);
    write_prefix_kernel<<<dim3(NCHUNKS, NHEADS), 64>>>(Wh1, NHEADS * NHID, NHID, perm, w,
                                                       chunkP, chunkS, P, S);
    apply_attn_kernel<<<(NN * NHEADS * 64) / 256, 256>>>(key, f1, P, S, meanb, NHID, NHEADS,
                                                         H, NHEADS * NHID);

    // ---------------- layer 2 (output head, F = 40) ----------------
    {
        dim3 grid((NCLASS + BN - 1) / BN, (NN + BM - 1) / BM);
        sgemm_kernel<<<grid, 256>>>(NN, NCLASS, NHEADS * NHID, H, W_out, Wh2);
    }
    compute_f_kernel<<<(NN * 32 + 127) / 128, 128>>>(Wh2, NCLASS, NCLASS, a_out, 2 * NCLASS, 1, f1, f2);
    sort_desc_kernel<<<1, 1024>>>(f2, key, perm);
    compute_w_kernel<<<(NN + 255) / 256, 256>>>(key, w, 1);
    col_mean_kernel<<<dim3(NCLASS, 1), 256>>>(Wh2, NCLASS, NCLASS, meanb);
    chunk_sums_kernel<<<dim3(NCHUNKS, 1), 64>>>(Wh2, NCLASS, NCLASS, perm, w, chunkP, chunkS);
    scan_chunks_kernel<<<1, 64>>>(chunkP, chunkS, NCLASS);
    write_prefix_kernel<<<dim3(NCHUNKS, 1), 64>>>(Wh2, NCLASS, NCLASS, perm, w, chunkP, chunkS, P2, S2);
    apply_attn_kernel<<<(NN * 64) / 256, 256>>>(key, f1, P2, S2, meanb, NCLASS, 1, O2, NCLASS);

    log_softmax_kernel<<<(NN + 7) / 8, 256>>>(O2, out);
}